// round 17
// baseline (speedup 1.0000x reference)
#include <cuda_runtime.h>
#include <cuda_bf16.h>
#include <mma.h>
#include <math.h>
#include <stdint.h>

using namespace nvcuda;

// Shapes (fixed): U=256, D=5120, N=16, R=160
#define U_DIM 256
#define D_DIM 5120
#define N_DIM 16
#define R_DIM 160
#define NCOL  176   // 160 (t) + 16 (B)
#define NPADW 192   // padded combined-W cols (11 valid n16 tiles + 1 zero)

typedef unsigned long long ull;

// ---------------- scratch ----------------
#define S1_SPLITS 64
#define S1_KC     80      // K per split = 5 chunks of 16
#define S1_NCH    5
#define S1_M      64      // users per block

__device__ __align__(16) float g_partial[S1_SPLITS * U_DIM * NCOL];  // 11.5 MB
__device__ __align__(16) float g_tbuf[U_DIM * NCOL];                 // t | B fp32
__device__ __align__(16) float g_c1[U_DIM * D_DIM];                  // 5 MB dt*x
__device__ __align__(16) __nv_bfloat16 g_xh[U_DIM * D_DIM];          // 2.6 MB
__device__ __align__(16) __nv_bfloat16 g_xl[U_DIM * D_DIM];
__device__ __align__(16) __nv_bfloat16 g_wh[D_DIM * NPADW];          // 2.0 MB
__device__ __align__(16) __nv_bfloat16 g_wl[D_DIM * NPADW];
__device__ __align__(16) __nv_bfloat16 g_w2h[R_DIM * D_DIM];         // 1.6 MB
__device__ __align__(16) __nv_bfloat16 g_w2l[R_DIM * D_DIM];
__device__ __align__(16) __nv_bfloat16 g_th[U_DIM * R_DIM];          // 80 KB
__device__ __align__(16) __nv_bfloat16 g_tl[U_DIM * R_DIM];

// ================= Stage 0: fp32 -> bf16 hi/lo conversion =======================
#define XG  (U_DIM * D_DIM / 4)        // 327680
#define WG  (D_DIM * NPADW / 4)        // 245760
#define W2G (R_DIM * D_DIM / 4)        // 204800
#define CV_TOTAL (XG + WG + W2G)       // 778240
#define CV_BLOCKS (CV_TOTAL / 256)     // 3040

__global__ void __launch_bounds__(256) convert_kernel(
    const float* __restrict__ x,
    const float* __restrict__ W1,   // [5120,160]
    const float* __restrict__ Bp,   // [5120,16]
    const float* __restrict__ W2)   // [160,5120]
{
    const int gidx = blockIdx.x * 256 + threadIdx.x;
    float4 v;
    uint2 *dh, *dl;
    if (gidx < XG) {
        v = ((const float4*)x)[gidx];
        dh = (uint2*)g_xh + gidx;
        dl = (uint2*)g_xl + gidx;
    } else if (gidx < XG + WG) {
        const int j = gidx - XG;
        const int k = j / (NPADW / 4);
        const int c = (j - k * (NPADW / 4)) * 4;
        if (c < R_DIM)      v = *(const float4*)(W1 + (size_t)k * R_DIM + c);
        else if (c < NCOL)  v = *(const float4*)(Bp + (size_t)k * N_DIM + (c - R_DIM));
        else                v = make_float4(0.f, 0.f, 0.f, 0.f);
        dh = (uint2*)g_wh + j;
        dl = (uint2*)g_wl + j;
    } else {
        const int j = gidx - XG - WG;
        v = ((const float4*)W2)[j];
        dh = (uint2*)g_w2h + j;
        dl = (uint2*)g_w2l + j;
    }
    __nv_bfloat162 h01 = __floats2bfloat162_rn(v.x, v.y);
    __nv_bfloat162 h23 = __floats2bfloat162_rn(v.z, v.w);
    float l0 = v.x - __bfloat162float(__low2bfloat16(h01));
    float l1 = v.y - __bfloat162float(__high2bfloat16(h01));
    float l2 = v.z - __bfloat162float(__low2bfloat16(h23));
    float l3 = v.w - __bfloat162float(__high2bfloat16(h23));
    __nv_bfloat162 l01 = __floats2bfloat162_rn(l0, l1);
    __nv_bfloat162 l23 = __floats2bfloat162_rn(l2, l3);
    uint2 ph, pl;
    ph.x = *(uint32_t*)&h01; ph.y = *(uint32_t*)&h23;
    pl.x = *(uint32_t*)&l01; pl.y = *(uint32_t*)&l23;
    *dh = ph;
    *dl = pl;
}

// ================= Stage 1: wmma GEMM, frags direct from global =================
// C[256,176] = x @ [W1|Bp].  grid (4 u-tiles, 64 splits), 8 warps, NO smem/syncs.
__global__ void __launch_bounds__(256) stage1_wmma(void)
{
    const int wid = threadIdx.x >> 5;
    const int u0  = blockIdx.x * S1_M;
    const int k0  = blockIdx.y * S1_KC;

    const int mrow = wid >> 1;            // 0..3
    const int jt0  = (wid & 1) * 6;       // 0 or 6
    const int jcnt = (wid & 1) ? 5 : 6;

    wmma::fragment<wmma::accumulator, 16, 16, 16, float> cf[6];
#pragma unroll
    for (int j = 0; j < 6; ++j) wmma::fill_fragment(cf[j], 0.f);

    const __nv_bfloat16* xh = g_xh + (size_t)(u0 + mrow * 16) * D_DIM;
    const __nv_bfloat16* xl = g_xl + (size_t)(u0 + mrow * 16) * D_DIM;

#pragma unroll
    for (int s = 0; s < S1_NCH; ++s) {
        const int k = k0 + s * 16;
        wmma::fragment<wmma::matrix_a, 16, 16, 16, __nv_bfloat16, wmma::row_major> ah, al;
        wmma::load_matrix_sync(ah, xh + k, D_DIM);
        wmma::load_matrix_sync(al, xl + k, D_DIM);
#pragma unroll
        for (int j = 0; j < 6; ++j) {
            if (j < jcnt) {
                const int jt = jt0 + j;
                wmma::fragment<wmma::matrix_b, 16, 16, 16, __nv_bfloat16, wmma::row_major> bh, bl;
                wmma::load_matrix_sync(bh, g_wh + (size_t)k * NPADW + jt * 16, NPADW);
                wmma::load_matrix_sync(bl, g_wl + (size_t)k * NPADW + jt * 16, NPADW);
                wmma::mma_sync(cf[j], ah, bh, cf[j]);
                wmma::mma_sync(cf[j], al, bh, cf[j]);
                wmma::mma_sync(cf[j], ah, bl, cf[j]);
            }
        }
    }

    float* pout = g_partial + (size_t)blockIdx.y * (U_DIM * NCOL)
                + (size_t)(u0 + mrow * 16) * NCOL;
#pragma unroll
    for (int j = 0; j < 6; ++j) {
        if (j < jcnt) {
            wmma::store_matrix_sync(pout + (jt0 + j) * 16, cf[j], NCOL, wmma::mem_row_major);
        }
    }
}

// ================= Stage 2: reduce 64 partials; emit t bf16 hi/lo ===============
#define RED_F4 (U_DIM * NCOL / 4)   // 11264
__global__ void __launch_bounds__(256) reduce_kernel() {
    const int idx = blockIdx.x * 256 + threadIdx.x;   // 44 blocks
    const float4* p4 = (const float4*)g_partial;
    float4 s = make_float4(0.f, 0.f, 0.f, 0.f);
#pragma unroll 8
    for (int sp = 0; sp < S1_SPLITS; ++sp) {
        float4 v = __ldcg(p4 + (size_t)sp * RED_F4 + idx);
        s.x += v.x; s.y += v.y; s.z += v.z; s.w += v.w;
    }
    ((float4*)g_tbuf)[idx] = s;

    // cols 0..159 -> t bf16 hi/lo at [u][160]
    const int u = idx / (NCOL / 4);
    const int c = (idx - u * (NCOL / 4)) * 4;
    if (c < R_DIM) {
        __nv_bfloat162 h01 = __floats2bfloat162_rn(s.x, s.y);
        __nv_bfloat162 h23 = __floats2bfloat162_rn(s.z, s.w);
        float l0 = s.x - __bfloat162float(__low2bfloat16(h01));
        float l1 = s.y - __bfloat162float(__high2bfloat16(h01));
        float l2 = s.z - __bfloat162float(__low2bfloat16(h23));
        float l3 = s.w - __bfloat162float(__high2bfloat16(h23));
        __nv_bfloat162 l01 = __floats2bfloat162_rn(l0, l1);
        __nv_bfloat162 l23 = __floats2bfloat162_rn(l2, l3);
        uint2 ph, pl;
        ph.x = *(uint32_t*)&h01; ph.y = *(uint32_t*)&h23;
        pl.x = *(uint32_t*)&l01; pl.y = *(uint32_t*)&l23;
        *((uint2*)(g_th + (size_t)u * R_DIM + c)) = ph;
        *((uint2*)(g_tl + (size_t)u * R_DIM + c)) = pl;
    }
}

// ================= Stage 3: dt wmma GEMM -> softplus*x -> g_c1 ==================
// z[256,5120] = t @ W2. grid 160 blocks (32-d strip each, ALL 256 u). 8 warps:
// warp w: n-tile j = 2*bid + (w&1), m-quarter q = w>>1 (m-tiles q*4..q*4+3).
__global__ void __launch_bounds__(256) dt_wmma(
    const float* __restrict__ bias,  // [5120]
    const float* __restrict__ x)     // [256,5120]
{
    __shared__ __align__(16) float zsm[U_DIM * 32];   // 32 KB: [u][32 d]
    __shared__ float bias_s[32];

    const int tid = threadIdx.x;
    const int wid = tid >> 5;
    const int d0  = blockIdx.x * 32;

    if (tid < 32) bias_s[tid] = bias[d0 + tid];

    const int jh = wid & 1;               // d half (16 cols)
    const int q  = wid >> 1;              // m quarter
    const int nb = d0 + jh * 16;          // W2 col base

    wmma::fragment<wmma::accumulator, 16, 16, 16, float> cf[4];
#pragma unroll
    for (int m = 0; m < 4; ++m) wmma::fill_fragment(cf[m], 0.f);

#pragma unroll
    for (int c = 0; c < 10; ++c) {
        const int k = c * 16;
        wmma::fragment<wmma::matrix_b, 16, 16, 16, __nv_bfloat16, wmma::row_major> bh, bl;
        wmma::load_matrix_sync(bh, g_w2h + (size_t)k * D_DIM + nb, D_DIM);
        wmma::load_matrix_sync(bl, g_w2l + (size_t)k * D_DIM + nb, D_DIM);
#pragma unroll
        for (int m = 0; m < 4; ++m) {
            const int mt = q * 4 + m;
            wmma::fragment<wmma::matrix_a, 16, 16, 16, __nv_bfloat16, wmma::row_major> ah, al;
            wmma::load_matrix_sync(ah, g_th + (size_t)(mt * 16) * R_DIM + k, R_DIM);
            wmma::load_matrix_sync(al, g_tl + (size_t)(mt * 16) * R_DIM + k, R_DIM);
            wmma::mma_sync(cf[m], ah, bh, cf[m]);
            wmma::mma_sync(cf[m], al, bh, cf[m]);
            wmma::mma_sync(cf[m], ah, bl, cf[m]);
        }
    }

    // store z tiles to smem: rows (q*4+m)*16.., cols jh*16..
#pragma unroll
    for (int m = 0; m < 4; ++m) {
        const int mt = q * 4 + m;
        wmma::store_matrix_sync(zsm + (size_t)(mt * 16) * 32 + jh * 16, cf[m],
                                32, wmma::mem_row_major);
    }
    __syncthreads();

    // epilogue: c1 = softplus(z + bias) * x
    const int dl = tid & 31;
    const int ur = tid >> 5;      // 0..7
    const float bz = bias_s[dl];
#pragma unroll 4
    for (int i = 0; i < 32; ++i) {
        const int u = i * 8 + ur;
        const float z = zsm[u * 32 + dl] + bz;
        const float dt = fmaxf(z, 0.f) + log1pf(expf(-fabsf(z)));
        const size_t gi = (size_t)u * D_DIM + d0 + dl;
        g_c1[gi] = dt * __ldg(x + gi);
    }
}

// ================= Stage 4: pure stream (R3 proven 35.3us) ======================
__global__ void __launch_bounds__(256) stream_kernel(
    const float4* __restrict__ abar4,
    const float4* __restrict__ hst4,
    float4* __restrict__ out4)
{
    const int bid = blockIdx.x;
    const int t   = threadIdx.x;
    const int u   = bid / 20;
    const size_t wb = (size_t)bid * 1024 + (size_t)(t >> 5) * 128 + (t & 31);

    const float4* Bu = (const float4*)(g_tbuf + u * NCOL + R_DIM);
    const float4 b = __ldg(Bu + (t & 3));

#pragma unroll
    for (int j = 0; j < 4; ++j) {
        const size_t f = wb + 32 * j;
        const float c1 = __ldg(g_c1 + (f >> 2));
        const float4 a = __ldcs(abar4 + f);
        const float4 h = __ldcs(hst4 + f);
        float4 o;
        o.x = fmaf(a.x, h.x, c1 * b.x);
        o.y = fmaf(a.y, h.y, c1 * b.y);
        o.z = fmaf(a.z, h.z, c1 * b.z);
        o.w = fmaf(a.w, h.w, c1 * b.w);
        __stcs(out4 + f, o);
    }
}

extern "C" void kernel_launch(void* const* d_in, const int* in_sizes, int n_in,
                              void* d_out, int out_size) {
    const float* x    = (const float*)d_in[0];   // [256,5120]
    const float* W1   = (const float*)d_in[1];   // [5120,160]
    const float* W2   = (const float*)d_in[2];   // [160,5120]
    const float* bias = (const float*)d_in[3];   // [5120]
    const float* Bp   = (const float*)d_in[4];   // [5120,16]
    const float* abar = (const float*)d_in[5];   // [256,5120,16]
    const float* hst  = (const float*)d_in[6];   // [256,5120,16]
    float* out = (float*)d_out;

    convert_kernel<<<CV_BLOCKS, 256>>>(x, W1, Bp, W2);
    stage1_wmma<<<dim3(U_DIM / S1_M, S1_SPLITS), 256>>>();
    reduce_kernel<<<RED_F4 / 256, 256>>>();
    dt_wmma<<<D_DIM / 32, 256>>>(bias, x);
    stream_kernel<<<U_DIM * 20, 256>>>(
        (const float4*)abar, (const float4*)hst, (float4*)out);
}